// round 6
// baseline (speedup 1.0000x reference)
#include <cuda_runtime.h>
#include <cuda_bf16.h>
#include <cstdint>
#include <stddef.h>
#include <math.h>

#define B_DIM 1024
#define L_DIM 1024
#define O_DIM 4096
#define N_ITERS 20
#define INF_LR   0.01f
#define SPARSE_Z 1e-3f

typedef unsigned short u16;
typedef uint32_t u32;

// ---------------- scratch (no cudaMalloc allowed) ----------------
__device__ u16   g_Whi [O_DIM * L_DIM];
__device__ u16   g_Wlo [O_DIM * L_DIM];
__device__ u16   g_WThi[L_DIM * O_DIM];
__device__ u16   g_WTlo[L_DIM * O_DIM];
__device__ u16   g_Ghi [B_DIM * O_DIM];
__device__ u16   g_Glo [B_DIM * O_DIM];
__device__ float g_zf  [B_DIM * L_DIM];
__device__ u16   g_zhi [B_DIM * L_DIM];
__device__ u16   g_zlo [B_DIM * L_DIM];

// ---------------- helpers ----------------
__device__ __forceinline__ u32 smem_u32(const void* p) {
    u32 a;
    asm("{ .reg .u64 t; cvta.to.shared.u64 t, %1; cvt.u32.u64 %0, t; }" : "=r"(a) : "l"(p));
    return a;
}
__device__ __forceinline__ void cp16(u32 dst, const void* src) {
    asm volatile("cp.async.cg.shared.global [%0], [%1], 16;" :: "r"(dst), "l"(src));
}
__device__ __forceinline__ void cp_commit() { asm volatile("cp.async.commit_group;"); }
template <int N> __device__ __forceinline__ void cp_wait() {
    asm volatile("cp.async.wait_group %0;" :: "n"(N));
}
__device__ __forceinline__ void ldsm4(u32* r, u32 a) {
    asm volatile("ldmatrix.sync.aligned.m8n8.x4.shared.b16 {%0,%1,%2,%3}, [%4];"
                 : "=r"(r[0]), "=r"(r[1]), "=r"(r[2]), "=r"(r[3]) : "r"(a));
}
__device__ __forceinline__ void mma_bf16(float* d, const u32* a, u32 b0, u32 b1) {
    asm volatile(
        "mma.sync.aligned.m16n8k16.row.col.f32.bf16.bf16.f32 "
        "{%0,%1,%2,%3},{%4,%5,%6,%7},{%8,%9},{%0,%1,%2,%3};"
        : "+f"(d[0]), "+f"(d[1]), "+f"(d[2]), "+f"(d[3])
        : "r"(a[0]), "r"(a[1]), "r"(a[2]), "r"(a[3]), "r"(b0), "r"(b1));
}
__device__ __forceinline__ void split2(float v, u16& h, u16& l) {
    __nv_bfloat16 bh = __float2bfloat16(v);
    h = __bfloat16_as_ushort(bh);
    l = __bfloat16_as_ushort(__float2bfloat16(v - __bfloat162float(bh)));
}
__device__ __forceinline__ u32 swz(u32 off) { return off ^ ((off >> 3) & 0x70u); }

// ---------------- one-time prep ----------------
__global__ void prep_w(const float* __restrict__ W,
                       u16* __restrict__ Whi, u16* __restrict__ Wlo,
                       u16* __restrict__ WThi, u16* __restrict__ WTlo) {
    __shared__ float t[32][33];
    int tx = threadIdx.x, ty = threadIdx.y;
    int lx = blockIdx.x * 32, oy = blockIdx.y * 32;
#pragma unroll
    for (int r = 0; r < 32; r += 8) {
        size_t idx = (size_t)(oy + ty + r) * L_DIM + lx + tx;
        float v = W[idx];
        u16 h, l; split2(v, h, l);
        Whi[idx] = h; Wlo[idx] = l;
        t[ty + r][tx] = v;
    }
    __syncthreads();
#pragma unroll
    for (int r = 0; r < 32; r += 8) {
        float v = t[tx][ty + r];
        size_t idx = (size_t)(lx + ty + r) * O_DIM + oy + tx;
        u16 h, l; split2(v, h, l);
        WThi[idx] = h; WTlo[idx] = l;
    }
}

__global__ void init_z(const float* __restrict__ mu, float* __restrict__ zf,
                       u16* __restrict__ zhi, u16* __restrict__ zlo) {
    int i = blockIdx.x * blockDim.x + threadIdx.x;
    float v = mu[i & (L_DIM - 1)];
    zf[i] = v;
    u16 h, l; split2(v, h, l);
    zhi[i] = h; zlo[i] = l;
}

// ---------------- pipelined bf16 split-GEMM with fused epilogue -------------
// C[m,n] = sum_k A[m,k]*B[n,k]   (A [M,K] k-contig, B [N,K] k-contig)
// 3-term split: Ahi*Bhi + Ahi*Blo + Alo*Bhi, fp32 accumulate.
// Split term is OUTERMOST in the MMA nest so same-acc MMAs are MF*4 apart
// (RAW distance >= HMMA latency/rt) instead of back-to-back.
// EPI=1: p=tanh(C); g=(1-p^2)*(X - p); write g as bf16 hi/lo (Ohi/Olo).
// EPI=2: z=X (fp32); zn = z - lr*((z-mu) - C + sz*sign(z));
//        write zf (OF1), bf16 hi/lo, and optionally OF2 (= d_out).
template <int BM, int BN, int NSTAGE, int EPI, int KDIM>
__global__ void __launch_bounds__(256, 1)
gemm_mma(const u16* __restrict__ Ah, const u16* __restrict__ Al,
         const u16* __restrict__ Bh, const u16* __restrict__ Bl,
         const float* X, const float* __restrict__ MU,
         u16* __restrict__ Ohi, u16* __restrict__ Olo,
         float* OF1, float* OF2) {
    constexpr int BK = 64, ROWB = 128;
    constexpr int MF = BM / 32;                       // warp M = BM/2, frags of 16
    constexpr int ABYTES = BM * ROWB, BBYTES = BN * ROWB;
    constexpr int STAGE = 2 * (ABYTES + BBYTES);
    constexpr int CPA = ABYTES / 16, CPB = BBYTES / 16;
    constexpr int TOT = 2 * (CPA + CPB);
    constexpr int S = KDIM / BK;
    static_assert(TOT % 256 == 0, "loader divisibility");

    extern __shared__ char sraw[];
    const u32 smem0 = (smem_u32(sraw) + 127u) & ~127u;

    const int tid = threadIdx.x, lane = tid & 31, wid = tid >> 5;
    const int wm = wid >> 2, wn = wid & 3;           // 2 x 4 warps
    const int bm = blockIdx.y * BM, bn = blockIdx.x * BN;

    auto load_stage = [&](int s, int buf) {
        const u32 sb = smem0 + (u32)buf * STAGE;
        const int k0 = s * BK;
#pragma unroll
        for (int i = 0; i < TOT / 256; i++) {
            int c = tid + i * 256;
            const u16* src; u32 tb; int local, rowbase;
            if (c < CPA)                 { src = Ah; tb = sb;                        local = c;                 rowbase = bm; }
            else if (c < 2 * CPA)        { src = Al; tb = sb + ABYTES;               local = c - CPA;           rowbase = bm; }
            else if (c < 2 * CPA + CPB)  { src = Bh; tb = sb + 2 * ABYTES;           local = c - 2 * CPA;       rowbase = bn; }
            else                         { src = Bl; tb = sb + 2 * ABYTES + BBYTES;  local = c - 2 * CPA - CPB; rowbase = bn; }
            int row = local >> 3, c16 = local & 7;
            cp16(tb + swz((u32)(row * ROWB + c16 * 16)),
                 src + (size_t)(rowbase + row) * KDIM + k0 + c16 * 8);
        }
    };

    float acc[MF][4][4];
#pragma unroll
    for (int a = 0; a < MF; a++)
#pragma unroll
        for (int b = 0; b < 4; b++)
#pragma unroll
            for (int k = 0; k < 4; k++) acc[a][b][k] = 0.f;

    // per-thread ldmatrix address components
    const int aRow = wm * (BM / 2) + (lane & 15);
    const int bRow = wn * 32 + lane;
    const u32 aOff = (u32)aRow * ROWB, aSx = ((u32)(aRow & 7)) << 4;
    const u32 aK = ((u32)(lane >> 4)) << 4;
    const u32 bOff = (u32)bRow * ROWB, bSx = ((u32)(bRow & 7)) << 4;

#pragma unroll
    for (int p = 0; p < NSTAGE - 1; p++) { load_stage(p, p); cp_commit(); }

    int cbuf = 0, lbuf = NSTAGE - 1;
    for (int s = 0; s < S; s++) {
        cp_wait<NSTAGE - 2>();
        __syncthreads();
        if (s + NSTAGE - 1 < S) load_stage(s + NSTAGE - 1, lbuf);
        cp_commit();
        if (++lbuf == NSTAGE) lbuf = 0;

        const u32 sb = smem0 + (u32)cbuf * STAGE;
        const u32 sAh = sb, sAl = sb + ABYTES;
        const u32 sBh = sb + 2 * ABYTES, sBl = sb + 2 * ABYTES + BBYTES;
#pragma unroll
        for (int ks = 0; ks < BK / 16; ks++) {
            const u32 ko  = (((u32)(ks * 32) + aK) ^ aSx);
            const u32 k0o = (((u32)(ks * 32)) ^ bSx);
            const u32 k1o = (((u32)(ks * 32 + 16)) ^ bSx);

            u32 ah[MF][4], al[MF][4];
            u32 bh0[4], bh1[4], bl0[4], bl1[4];

            // hi fragments first so term-1 MMAs can start ASAP
#pragma unroll
            for (int mf = 0; mf < MF; mf++)
                ldsm4(ah[mf], sAh + aOff + (u32)(mf * 16 * ROWB) + ko);
            ldsm4(bh0, sBh + bOff + k0o);
            ldsm4(bh1, sBh + bOff + k1o);
            // lo fragments (latency hidden under term-1 MMAs)
            ldsm4(bl0, sBl + bOff + k0o);
            ldsm4(bl1, sBl + bOff + k1o);
#pragma unroll
            for (int mf = 0; mf < MF; mf++)
                ldsm4(al[mf], sAl + aOff + (u32)(mf * 16 * ROWB) + ko);

            // term 1: Ahi * Bhi  (MF*4 independent accumulators)
#pragma unroll
            for (int mf = 0; mf < MF; mf++)
#pragma unroll
                for (int nf = 0; nf < 4; nf++)
                    mma_bf16(acc[mf][nf], ah[mf], bh0[nf], bh1[nf]);
            // term 2: Ahi * Blo
#pragma unroll
            for (int mf = 0; mf < MF; mf++)
#pragma unroll
                for (int nf = 0; nf < 4; nf++)
                    mma_bf16(acc[mf][nf], ah[mf], bl0[nf], bl1[nf]);
            // term 3: Alo * Bhi
#pragma unroll
            for (int mf = 0; mf < MF; mf++)
#pragma unroll
                for (int nf = 0; nf < 4; nf++)
                    mma_bf16(acc[mf][nf], al[mf], bh0[nf], bh1[nf]);
        }
        if (++cbuf == NSTAGE) cbuf = 0;
    }

    // ---- fused epilogue ----
    constexpr int OST = (EPI == 1) ? O_DIM : L_DIM;
#pragma unroll
    for (int mf = 0; mf < MF; mf++) {
#pragma unroll
        for (int nf = 0; nf < 4; nf++) {
            int r0 = bm + wm * (BM / 2) + mf * 16 + (lane >> 2);
            int cc = bn + wn * 32 + nf * 8 + (lane & 3) * 2;
#pragma unroll
            for (int h = 0; h < 2; h++) {
                int r = r0 + h * 8;
                float d0 = acc[mf][nf][2 * h], d1 = acc[mf][nf][2 * h + 1];
                size_t off = (size_t)r * OST + cc;
                if (EPI == 1) {
                    float2 xv = *(const float2*)(X + off);
                    float p0 = tanhf(d0), p1 = tanhf(d1);
                    float g0 = (1.f - p0 * p0) * (xv.x - p0);
                    float g1 = (1.f - p1 * p1) * (xv.y - p1);
                    u16 h0, l0, h1, l1;
                    split2(g0, h0, l0); split2(g1, h1, l1);
                    *(u32*)(Ohi + off) = (u32)h0 | ((u32)h1 << 16);
                    *(u32*)(Olo + off) = (u32)l0 | ((u32)l1 << 16);
                } else {
                    float2 zv = *(const float2*)(X + off);
                    float2 mv = *(const float2*)(MU + cc);
                    float s0 = (float)((zv.x > 0.f) - (zv.x < 0.f));
                    float s1 = (float)((zv.y > 0.f) - (zv.y < 0.f));
                    float zn0 = zv.x - INF_LR * ((zv.x - mv.x) - d0 + SPARSE_Z * s0);
                    float zn1 = zv.y - INF_LR * ((zv.y - mv.y) - d1 + SPARSE_Z * s1);
                    *(float2*)(OF1 + off) = make_float2(zn0, zn1);
                    u16 h0, l0, h1, l1;
                    split2(zn0, h0, l0); split2(zn1, h1, l1);
                    *(u32*)(Ohi + off) = (u32)h0 | ((u32)h1 << 16);
                    *(u32*)(Olo + off) = (u32)l0 | ((u32)l1 << 16);
                    if (OF2) *(float2*)(OF2 + off) = make_float2(zn0, zn1);
                }
            }
        }
    }
}

// ---------------- launch ----------------
extern "C" void kernel_launch(void* const* d_in, const int* in_sizes, int n_in,
                              void* d_out, int out_size) {
    const float* x  = (const float*)d_in[0];   // [B, O]
    const float* W  = (const float*)d_in[1];   // [O, L]
    const float* mu = (const float*)d_in[2];   // [L]
    // d_in[3] = inf_iters (device scalar; fixed at 20 by the problem spec,
    // unreadable on host under graph capture -> iterations unrolled as launches)
    float* out = (float*)d_out;                // [B, L]

    u16 *Whi, *Wlo, *WThi, *WTlo, *Ghi, *Glo, *zhi, *zlo;
    float* zf;
    cudaGetSymbolAddress((void**)&Whi,  g_Whi);
    cudaGetSymbolAddress((void**)&Wlo,  g_Wlo);
    cudaGetSymbolAddress((void**)&WThi, g_WThi);
    cudaGetSymbolAddress((void**)&WTlo, g_WTlo);
    cudaGetSymbolAddress((void**)&Ghi,  g_Ghi);
    cudaGetSymbolAddress((void**)&Glo,  g_Glo);
    cudaGetSymbolAddress((void**)&zf,   g_zf);
    cudaGetSymbolAddress((void**)&zhi,  g_zhi);
    cudaGetSymbolAddress((void**)&zlo,  g_zlo);

    constexpr int SM1 = 3 * 2 * (128 * 128 + 128 * 128);  // 196608
    constexpr int SM2 = 4 * 2 * (64 * 128 + 128 * 128);   // 196608

    cudaFuncSetAttribute(gemm_mma<128, 128, 3, 1, L_DIM>,
                         cudaFuncAttributeMaxDynamicSharedMemorySize, SM1 + 256);
    cudaFuncSetAttribute(gemm_mma<64, 128, 4, 2, O_DIM>,
                         cudaFuncAttributeMaxDynamicSharedMemorySize, SM2 + 256);

    prep_w<<<dim3(L_DIM / 32, O_DIM / 32), dim3(32, 8)>>>(W, Whi, Wlo, WThi, WTlo);
    init_z<<<(B_DIM * L_DIM) / 256, 256>>>(mu, zf, zhi, zlo);

    for (int it = 0; it < N_ITERS; ++it) {
        // GEMM1: C[b,o] = z @ W^T; fused tanh-deriv epilogue -> G (bf16 hi/lo)
        gemm_mma<128, 128, 3, 1, L_DIM>
            <<<dim3(O_DIM / 128, B_DIM / 128), 256, SM1 + 256>>>(
                zhi, zlo, Whi, Wlo, x, nullptr, Ghi, Glo, nullptr, nullptr);

        // GEMM2: C[b,l] = G @ W (B = WT[l,o]); fused z-update (in-place zf)
        gemm_mma<64, 128, 4, 2, O_DIM>
            <<<dim3(L_DIM / 128, B_DIM / 64), 256, SM2 + 256>>>(
                Ghi, Glo, WThi, WTlo, zf, mu, zhi, zlo, zf,
                (it == N_ITERS - 1) ? out : nullptr);
    }
}

// round 7
// speedup vs baseline: 1.0681x; 1.0681x over previous
#include <cuda_runtime.h>
#include <cuda_bf16.h>
#include <cstdint>
#include <stddef.h>
#include <math.h>

#define B_DIM 1024
#define L_DIM 1024
#define O_DIM 4096
#define N_ITERS 20
#define INF_LR   0.01f
#define SPARSE_Z 1e-3f

typedef unsigned short u16;
typedef uint32_t u32;

// ---------------- scratch (no cudaMalloc allowed) ----------------
__device__ u16   g_Whi [O_DIM * L_DIM];
__device__ u16   g_Wlo [O_DIM * L_DIM];
__device__ u16   g_WThi[L_DIM * O_DIM];
__device__ u16   g_WTlo[L_DIM * O_DIM];
__device__ u16   g_Ghi [B_DIM * O_DIM];
__device__ u16   g_Glo [B_DIM * O_DIM];
__device__ float g_zf  [B_DIM * L_DIM];
__device__ u16   g_zhi [B_DIM * L_DIM];
__device__ u16   g_zlo [B_DIM * L_DIM];

// ---------------- helpers ----------------
__device__ __forceinline__ u32 smem_u32(const void* p) {
    u32 a;
    asm("{ .reg .u64 t; cvta.to.shared.u64 t, %1; cvt.u32.u64 %0, t; }" : "=r"(a) : "l"(p));
    return a;
}
__device__ __forceinline__ void cp16(u32 dst, const void* src) {
    asm volatile("cp.async.cg.shared.global [%0], [%1], 16;" :: "r"(dst), "l"(src));
}
__device__ __forceinline__ void cp_commit() { asm volatile("cp.async.commit_group;"); }
template <int N> __device__ __forceinline__ void cp_wait() {
    asm volatile("cp.async.wait_group %0;" :: "n"(N));
}
__device__ __forceinline__ void ldsm4(u32* r, u32 a) {
    asm volatile("ldmatrix.sync.aligned.m8n8.x4.shared.b16 {%0,%1,%2,%3}, [%4];"
                 : "=r"(r[0]), "=r"(r[1]), "=r"(r[2]), "=r"(r[3]) : "r"(a));
}
__device__ __forceinline__ void mma_bf16(float* d, const u32* a, u32 b0, u32 b1) {
    asm volatile(
        "mma.sync.aligned.m16n8k16.row.col.f32.bf16.bf16.f32 "
        "{%0,%1,%2,%3},{%4,%5,%6,%7},{%8,%9},{%0,%1,%2,%3};"
        : "+f"(d[0]), "+f"(d[1]), "+f"(d[2]), "+f"(d[3])
        : "r"(a[0]), "r"(a[1]), "r"(a[2]), "r"(a[3]), "r"(b0), "r"(b1));
}
__device__ __forceinline__ void split2(float v, u16& h, u16& l) {
    __nv_bfloat16 bh = __float2bfloat16(v);
    h = __bfloat16_as_ushort(bh);
    l = __bfloat16_as_ushort(__float2bfloat16(v - __bfloat162float(bh)));
}
__device__ __forceinline__ u32 swz(u32 off) { return off ^ ((off >> 3) & 0x70u); }

// ---------------- one-time prep ----------------
__global__ void prep_w(const float* __restrict__ W,
                       u16* __restrict__ Whi, u16* __restrict__ Wlo,
                       u16* __restrict__ WThi, u16* __restrict__ WTlo) {
    __shared__ float t[32][33];
    int tx = threadIdx.x, ty = threadIdx.y;
    int lx = blockIdx.x * 32, oy = blockIdx.y * 32;
#pragma unroll
    for (int r = 0; r < 32; r += 8) {
        size_t idx = (size_t)(oy + ty + r) * L_DIM + lx + tx;
        float v = W[idx];
        u16 h, l; split2(v, h, l);
        Whi[idx] = h; Wlo[idx] = l;
        t[ty + r][tx] = v;
    }
    __syncthreads();
#pragma unroll
    for (int r = 0; r < 32; r += 8) {
        float v = t[tx][ty + r];
        size_t idx = (size_t)(lx + ty + r) * O_DIM + oy + tx;
        u16 h, l; split2(v, h, l);
        WThi[idx] = h; WTlo[idx] = l;
    }
}

__global__ void init_z(const float* __restrict__ mu, float* __restrict__ zf,
                       u16* __restrict__ zhi, u16* __restrict__ zlo) {
    int i = blockIdx.x * blockDim.x + threadIdx.x;
    float v = mu[i & (L_DIM - 1)];
    zf[i] = v;
    u16 h, l; split2(v, h, l);
    zhi[i] = h; zlo[i] = l;
}

// ---------------- pipelined bf16 split-GEMM with fused epilogue -------------
// C[m,n] = sum_k A[m,k]*B[n,k]   (A [M,K] k-contig, B [N,K] k-contig)
// 3-term split: Ahi*Bhi + Ahi*Blo + Alo*Bhi, fp32 accumulate.
// Sized for 2 CTAs/SM (96KB smem, <=128 regs) so cross-CTA warps hide
// smem latency and stage-boundary barriers.
// EPI=1: p=tanh(C); g=(1-p^2)*(X - p); write g as bf16 hi/lo (Ohi/Olo).
// EPI=2: z=X (fp32); zn = z - lr*((z-mu) - C + sz*sign(z));
//        write zf (OF1), bf16 hi/lo, and optionally OF2 (= d_out).
template <int BM, int BN, int NSTAGE, int EPI, int KDIM>
__global__ void __launch_bounds__(256, 2)
gemm_mma(const u16* __restrict__ Ah, const u16* __restrict__ Al,
         const u16* __restrict__ Bh, const u16* __restrict__ Bl,
         const float* X, const float* __restrict__ MU,
         u16* __restrict__ Ohi, u16* __restrict__ Olo,
         float* OF1, float* OF2) {
    constexpr int BK = 64, ROWB = 128;
    constexpr int MF = BM / 32;                       // warp M = BM/2, frags of 16
    constexpr int ABYTES = BM * ROWB, BBYTES = BN * ROWB;
    constexpr int STAGE = 2 * (ABYTES + BBYTES);
    constexpr int CPA = ABYTES / 16, CPB = BBYTES / 16;
    constexpr int TOT = 2 * (CPA + CPB);
    constexpr int S = KDIM / BK;
    static_assert(TOT % 256 == 0, "loader divisibility");

    extern __shared__ char sraw[];
    const u32 smem0 = (smem_u32(sraw) + 127u) & ~127u;

    const int tid = threadIdx.x, lane = tid & 31, wid = tid >> 5;
    const int wm = wid >> 2, wn = wid & 3;           // 2 x 4 warps
    const int bm = blockIdx.y * BM, bn = blockIdx.x * BN;

    auto load_stage = [&](int s, int buf) {
        const u32 sb = smem0 + (u32)buf * STAGE;
        const int k0 = s * BK;
#pragma unroll
        for (int i = 0; i < TOT / 256; i++) {
            int c = tid + i * 256;
            const u16* src; u32 tb; int local, rowbase;
            if (c < CPA)                 { src = Ah; tb = sb;                        local = c;                 rowbase = bm; }
            else if (c < 2 * CPA)        { src = Al; tb = sb + ABYTES;               local = c - CPA;           rowbase = bm; }
            else if (c < 2 * CPA + CPB)  { src = Bh; tb = sb + 2 * ABYTES;           local = c - 2 * CPA;       rowbase = bn; }
            else                         { src = Bl; tb = sb + 2 * ABYTES + BBYTES;  local = c - 2 * CPA - CPB; rowbase = bn; }
            int row = local >> 3, c16 = local & 7;
            cp16(tb + swz((u32)(row * ROWB + c16 * 16)),
                 src + (size_t)(rowbase + row) * KDIM + k0 + c16 * 8);
        }
    };

    float acc[MF][4][4];
#pragma unroll
    for (int a = 0; a < MF; a++)
#pragma unroll
        for (int b = 0; b < 4; b++)
#pragma unroll
            for (int k = 0; k < 4; k++) acc[a][b][k] = 0.f;

    // per-thread ldmatrix address components
    const int aRow = wm * (BM / 2) + (lane & 15);
    const int bRow = wn * 32 + lane;
    const u32 aOff = (u32)aRow * ROWB, aSx = ((u32)(aRow & 7)) << 4;
    const u32 aK = ((u32)(lane >> 4)) << 4;
    const u32 bOff = (u32)bRow * ROWB, bSx = ((u32)(bRow & 7)) << 4;

#pragma unroll
    for (int p = 0; p < NSTAGE - 1; p++) { load_stage(p, p); cp_commit(); }

    int cbuf = 0, lbuf = NSTAGE - 1;
    for (int s = 0; s < S; s++) {
        cp_wait<NSTAGE - 2>();
        __syncthreads();
        if (s + NSTAGE - 1 < S) load_stage(s + NSTAGE - 1, lbuf);
        cp_commit();
        if (++lbuf == NSTAGE) lbuf = 0;

        const u32 sb = smem0 + (u32)cbuf * STAGE;
        const u32 sAh = sb, sAl = sb + ABYTES;
        const u32 sBh = sb + 2 * ABYTES, sBl = sb + 2 * ABYTES + BBYTES;
#pragma unroll
        for (int ks = 0; ks < BK / 16; ks++) {
            const u32 ko  = (((u32)(ks * 32) + aK) ^ aSx);
            const u32 k0o = (((u32)(ks * 32)) ^ bSx);
            const u32 k1o = (((u32)(ks * 32 + 16)) ^ bSx);

            u32 ah[MF][4], al[MF][4];
            u32 bh0[4], bh1[4], bl0[4], bl1[4];

#pragma unroll
            for (int mf = 0; mf < MF; mf++)
                ldsm4(ah[mf], sAh + aOff + (u32)(mf * 16 * ROWB) + ko);
            ldsm4(bh0, sBh + bOff + k0o);
            ldsm4(bh1, sBh + bOff + k1o);
            ldsm4(bl0, sBl + bOff + k0o);
            ldsm4(bl1, sBl + bOff + k1o);
#pragma unroll
            for (int mf = 0; mf < MF; mf++)
                ldsm4(al[mf], sAl + aOff + (u32)(mf * 16 * ROWB) + ko);

            // term 1: Ahi * Bhi
#pragma unroll
            for (int mf = 0; mf < MF; mf++)
#pragma unroll
                for (int nf = 0; nf < 4; nf++)
                    mma_bf16(acc[mf][nf], ah[mf], bh0[nf], bh1[nf]);
            // term 2: Ahi * Blo
#pragma unroll
            for (int mf = 0; mf < MF; mf++)
#pragma unroll
                for (int nf = 0; nf < 4; nf++)
                    mma_bf16(acc[mf][nf], ah[mf], bl0[nf], bl1[nf]);
            // term 3: Alo * Bhi
#pragma unroll
            for (int mf = 0; mf < MF; mf++)
#pragma unroll
                for (int nf = 0; nf < 4; nf++)
                    mma_bf16(acc[mf][nf], al[mf], bh0[nf], bh1[nf]);
        }
        if (++cbuf == NSTAGE) cbuf = 0;
    }

    // ---- fused epilogue ----
    constexpr int OST = (EPI == 1) ? O_DIM : L_DIM;
#pragma unroll
    for (int mf = 0; mf < MF; mf++) {
#pragma unroll
        for (int nf = 0; nf < 4; nf++) {
            int r0 = bm + wm * (BM / 2) + mf * 16 + (lane >> 2);
            int cc = bn + wn * 32 + nf * 8 + (lane & 3) * 2;
#pragma unroll
            for (int h = 0; h < 2; h++) {
                int r = r0 + h * 8;
                float d0 = acc[mf][nf][2 * h], d1 = acc[mf][nf][2 * h + 1];
                size_t off = (size_t)r * OST + cc;
                if (EPI == 1) {
                    float2 xv = *(const float2*)(X + off);
                    float p0 = tanhf(d0), p1 = tanhf(d1);
                    float g0 = (1.f - p0 * p0) * (xv.x - p0);
                    float g1 = (1.f - p1 * p1) * (xv.y - p1);
                    u16 h0, l0, h1, l1;
                    split2(g0, h0, l0); split2(g1, h1, l1);
                    *(u32*)(Ohi + off) = (u32)h0 | ((u32)h1 << 16);
                    *(u32*)(Olo + off) = (u32)l0 | ((u32)l1 << 16);
                } else {
                    float2 zv = *(const float2*)(X + off);
                    float2 mv = *(const float2*)(MU + cc);
                    float s0 = (float)((zv.x > 0.f) - (zv.x < 0.f));
                    float s1 = (float)((zv.y > 0.f) - (zv.y < 0.f));
                    float zn0 = zv.x - INF_LR * ((zv.x - mv.x) - d0 + SPARSE_Z * s0);
                    float zn1 = zv.y - INF_LR * ((zv.y - mv.y) - d1 + SPARSE_Z * s1);
                    *(float2*)(OF1 + off) = make_float2(zn0, zn1);
                    u16 h0, l0, h1, l1;
                    split2(zn0, h0, l0); split2(zn1, h1, l1);
                    *(u32*)(Ohi + off) = (u32)h0 | ((u32)h1 << 16);
                    *(u32*)(Olo + off) = (u32)l0 | ((u32)l1 << 16);
                    if (OF2) *(float2*)(OF2 + off) = make_float2(zn0, zn1);
                }
            }
        }
    }
}

// ---------------- launch ----------------
extern "C" void kernel_launch(void* const* d_in, const int* in_sizes, int n_in,
                              void* d_out, int out_size) {
    const float* x  = (const float*)d_in[0];   // [B, O]
    const float* W  = (const float*)d_in[1];   // [O, L]
    const float* mu = (const float*)d_in[2];   // [L]
    // d_in[3] = inf_iters (device scalar; fixed at 20 by the problem spec,
    // unreadable on host under graph capture -> iterations unrolled as launches)
    float* out = (float*)d_out;                // [B, L]

    u16 *Whi, *Wlo, *WThi, *WTlo, *Ghi, *Glo, *zhi, *zlo;
    float* zf;
    cudaGetSymbolAddress((void**)&Whi,  g_Whi);
    cudaGetSymbolAddress((void**)&Wlo,  g_Wlo);
    cudaGetSymbolAddress((void**)&WThi, g_WThi);
    cudaGetSymbolAddress((void**)&WTlo, g_WTlo);
    cudaGetSymbolAddress((void**)&Ghi,  g_Ghi);
    cudaGetSymbolAddress((void**)&Glo,  g_Glo);
    cudaGetSymbolAddress((void**)&zf,   g_zf);
    cudaGetSymbolAddress((void**)&zhi,  g_zhi);
    cudaGetSymbolAddress((void**)&zlo,  g_zlo);

    // STAGE = 2*(64*128 + 128*128) = 49152 B; 2 stages = 96KB -> 2 CTAs/SM
    constexpr int SMEM = 2 * 2 * (64 * 128 + 128 * 128) + 256;

    cudaFuncSetAttribute(gemm_mma<64, 128, 2, 1, L_DIM>,
                         cudaFuncAttributeMaxDynamicSharedMemorySize, SMEM);
    cudaFuncSetAttribute(gemm_mma<64, 128, 2, 2, O_DIM>,
                         cudaFuncAttributeMaxDynamicSharedMemorySize, SMEM);

    prep_w<<<dim3(L_DIM / 32, O_DIM / 32), dim3(32, 8)>>>(W, Whi, Wlo, WThi, WTlo);
    init_z<<<(B_DIM * L_DIM) / 256, 256>>>(mu, zf, zhi, zlo);

    for (int it = 0; it < N_ITERS; ++it) {
        // GEMM1: C[b,o] = z @ W^T; fused tanh-deriv epilogue -> G (bf16 hi/lo)
        gemm_mma<64, 128, 2, 1, L_DIM>
            <<<dim3(O_DIM / 128, B_DIM / 64), 256, SMEM>>>(
                zhi, zlo, Whi, Wlo, x, nullptr, Ghi, Glo, nullptr, nullptr);

        // GEMM2: C[b,l] = G @ W (B = WT[l,o]); fused z-update (in-place zf)
        gemm_mma<64, 128, 2, 2, O_DIM>
            <<<dim3(L_DIM / 128, B_DIM / 64), 256, SMEM>>>(
                Ghi, Glo, WThi, WTlo, zf, mu, zhi, zlo, zf,
                (it == N_ITERS - 1) ? out : nullptr);
    }
}

// round 8
// speedup vs baseline: 1.1042x; 1.0338x over previous
#include <cuda_runtime.h>
#include <cuda_bf16.h>
#include <cstdint>
#include <stddef.h>
#include <math.h>

#define B_DIM 1024
#define L_DIM 1024
#define O_DIM 4096
#define N_ITERS 20
#define INF_LR   0.01f
#define SPARSE_Z 1e-3f

typedef unsigned short u16;
typedef uint32_t u32;

// ---------------- scratch (no cudaMalloc allowed) ----------------
__device__ u16   g_Whi [O_DIM * L_DIM];
__device__ u16   g_Wlo [O_DIM * L_DIM];
__device__ u16   g_WThi[L_DIM * O_DIM];
__device__ u16   g_WTlo[L_DIM * O_DIM];
__device__ u16   g_Ghi [B_DIM * O_DIM];
__device__ u16   g_Glo [B_DIM * O_DIM];
__device__ float g_zf  [B_DIM * L_DIM];
__device__ u16   g_zhi [B_DIM * L_DIM];
__device__ u16   g_zlo [B_DIM * L_DIM];
__device__ float g_part[4 * B_DIM * L_DIM];   // split-K partials (16MB)

// ---------------- helpers ----------------
__device__ __forceinline__ u32 smem_u32(const void* p) {
    u32 a;
    asm("{ .reg .u64 t; cvta.to.shared.u64 t, %1; cvt.u32.u64 %0, t; }" : "=r"(a) : "l"(p));
    return a;
}
__device__ __forceinline__ void cp16(u32 dst, const void* src) {
    asm volatile("cp.async.cg.shared.global [%0], [%1], 16;" :: "r"(dst), "l"(src));
}
__device__ __forceinline__ void cp_commit() { asm volatile("cp.async.commit_group;"); }
template <int N> __device__ __forceinline__ void cp_wait() {
    asm volatile("cp.async.wait_group %0;" :: "n"(N));
}
__device__ __forceinline__ void ldsm4(u32* r, u32 a) {
    asm volatile("ldmatrix.sync.aligned.m8n8.x4.shared.b16 {%0,%1,%2,%3}, [%4];"
                 : "=r"(r[0]), "=r"(r[1]), "=r"(r[2]), "=r"(r[3]) : "r"(a));
}
__device__ __forceinline__ void mma_bf16(float* d, const u32* a, u32 b0, u32 b1) {
    asm volatile(
        "mma.sync.aligned.m16n8k16.row.col.f32.bf16.bf16.f32 "
        "{%0,%1,%2,%3},{%4,%5,%6,%7},{%8,%9},{%0,%1,%2,%3};"
        : "+f"(d[0]), "+f"(d[1]), "+f"(d[2]), "+f"(d[3])
        : "r"(a[0]), "r"(a[1]), "r"(a[2]), "r"(a[3]), "r"(b0), "r"(b1));
}
__device__ __forceinline__ void split2(float v, u16& h, u16& l) {
    __nv_bfloat16 bh = __float2bfloat16(v);
    h = __bfloat16_as_ushort(bh);
    l = __bfloat16_as_ushort(__float2bfloat16(v - __bfloat162float(bh)));
}
__device__ __forceinline__ u32 swz(u32 off) { return off ^ ((off >> 3) & 0x70u); }

// ---------------- one-time prep ----------------
__global__ void prep_w(const float* __restrict__ W,
                       u16* __restrict__ Whi, u16* __restrict__ Wlo,
                       u16* __restrict__ WThi, u16* __restrict__ WTlo) {
    __shared__ float t[32][33];
    int tx = threadIdx.x, ty = threadIdx.y;
    int lx = blockIdx.x * 32, oy = blockIdx.y * 32;
#pragma unroll
    for (int r = 0; r < 32; r += 8) {
        size_t idx = (size_t)(oy + ty + r) * L_DIM + lx + tx;
        float v = W[idx];
        u16 h, l; split2(v, h, l);
        Whi[idx] = h; Wlo[idx] = l;
        t[ty + r][tx] = v;
    }
    __syncthreads();
#pragma unroll
    for (int r = 0; r < 32; r += 8) {
        float v = t[tx][ty + r];
        size_t idx = (size_t)(lx + ty + r) * O_DIM + oy + tx;
        u16 h, l; split2(v, h, l);
        WThi[idx] = h; WTlo[idx] = l;
    }
}

__global__ void init_z(const float* __restrict__ mu, float* __restrict__ zf,
                       u16* __restrict__ zhi, u16* __restrict__ zlo) {
    int i = blockIdx.x * blockDim.x + threadIdx.x;
    float v = mu[i & (L_DIM - 1)];
    zf[i] = v;
    u16 h, l; split2(v, h, l);
    zhi[i] = h; zlo[i] = l;
}

// ------------- big-warp-tile bf16 split-GEMM (CTA 128x256, warp 64x64) ------
// C[m,n] = sum_k A[m,k]*B[n,k]; 3-term split hi*hi + hi*lo + lo*hi.
// bytes/MMA = 117 < 128 B/cyc smem parity -> smem crossbar no longer caps.
// KROW: global K stride of A/B rows. KLEN: K span per CTA (blockIdx.z selects
// the K chunk for split-K).
// EPI=1: p=tanh(C); g=(1-p^2)*(X-p); write bf16 hi/lo.
// EPI=0: write raw fp32 partial to OF1 + blockIdx.z*(B*L).
template <int EPI, int KROW, int KLEN>
__global__ void __launch_bounds__(256, 1)
gemm_big(const u16* __restrict__ Ah, const u16* __restrict__ Al,
         const u16* __restrict__ Bh, const u16* __restrict__ Bl,
         const float* __restrict__ X,
         u16* __restrict__ Ohi, u16* __restrict__ Olo,
         float* __restrict__ OF1) {
    constexpr int BM = 128, BN = 256, BK = 64, ROWB = 128;
    constexpr int ABYTES = BM * ROWB;          // 16384
    constexpr int BBYTES = BN * ROWB;          // 32768
    constexpr int STAGE  = 2 * (ABYTES + BBYTES);  // 98304
    constexpr int CPA = ABYTES / 16, CPB = BBYTES / 16;
    constexpr int TOT = 2 * (CPA + CPB);       // 6144
    constexpr int S = KLEN / BK;               // 16

    extern __shared__ char sraw[];
    const u32 smem0 = (smem_u32(sraw) + 127u) & ~127u;

    const int tid = threadIdx.x, lane = tid & 31, wid = tid >> 5;
    const int wm = wid >> 2, wn = wid & 3;     // 2 x 4 warps, warp tile 64x64
    const int bm = blockIdx.y * BM, bn = blockIdx.x * BN;
    const int kbase = blockIdx.z * S;

    auto load_stage = [&](int s, int buf) {
        const u32 sb = smem0 + (u32)buf * STAGE;
        const int k0 = (kbase + s) * BK;
#pragma unroll
        for (int i = 0; i < TOT / 256; i++) {
            int c = tid + i * 256;
            const u16* src; u32 tb; int local, rowbase;
            if (c < CPA)                 { src = Ah; tb = sb;                        local = c;                 rowbase = bm; }
            else if (c < 2 * CPA)        { src = Al; tb = sb + ABYTES;               local = c - CPA;           rowbase = bm; }
            else if (c < 2 * CPA + CPB)  { src = Bh; tb = sb + 2 * ABYTES;           local = c - 2 * CPA;       rowbase = bn; }
            else                         { src = Bl; tb = sb + 2 * ABYTES + BBYTES;  local = c - 2 * CPA - CPB; rowbase = bn; }
            int row = local >> 3, c16 = local & 7;
            cp16(tb + swz((u32)(row * ROWB + c16 * 16)),
                 src + (size_t)(rowbase + row) * KROW + k0 + c16 * 8);
        }
    };

    float acc[4][8][4];
#pragma unroll
    for (int a = 0; a < 4; a++)
#pragma unroll
        for (int b = 0; b < 8; b++)
#pragma unroll
            for (int k = 0; k < 4; k++) acc[a][b][k] = 0.f;

    // ldmatrix address components
    const u32 sx  = ((u32)(lane & 7)) << 4;                  // swizzle XOR
    const u32 aOff = (u32)((wm * 64 + (lane & 15)) * ROWB);  // +mf*16*ROWB
    const u32 aK   = ((u32)(lane >> 4)) << 4;
    const u32 bOff = (u32)((wn * 64 + lane) * ROWB);         // +half*32*ROWB

    load_stage(0, 0); cp_commit();

    int cbuf = 0, lbuf = 1;
    for (int s = 0; s < S; s++) {
        cp_wait<0>();
        __syncthreads();
        if (s + 1 < S) load_stage(s + 1, lbuf);
        cp_commit();
        lbuf ^= 1;

        const u32 sb = smem0 + (u32)cbuf * STAGE;
        const u32 sAh = sb, sAl = sb + ABYTES;
        const u32 sBh = sb + 2 * ABYTES, sBl = sb + 2 * ABYTES + BBYTES;
#pragma unroll
        for (int ks = 0; ks < BK / 16; ks++) {
            const u32 ko  = (((u32)(ks * 32) + aK) ^ sx);
            const u32 k0o = (((u32)(ks * 32)) ^ sx);
            const u32 k1o = (((u32)(ks * 32 + 16)) ^ sx);

            u32 ah[4][4], al[4][4];
#pragma unroll
            for (int mf = 0; mf < 4; mf++) {
                ldsm4(ah[mf], sAh + aOff + (u32)(mf * 16 * ROWB) + ko);
                ldsm4(al[mf], sAl + aOff + (u32)(mf * 16 * ROWB) + ko);
            }
#pragma unroll
            for (int half = 0; half < 2; half++) {
                const u32 bo = bOff + (u32)(half * 32 * ROWB);
                u32 bh0[4], bh1[4], bl0[4], bl1[4];
                ldsm4(bh0, sBh + bo + k0o);
                ldsm4(bh1, sBh + bo + k1o);
                ldsm4(bl0, sBl + bo + k0o);
                ldsm4(bl1, sBl + bo + k1o);
                // term 1: Ahi*Bhi
#pragma unroll
                for (int mf = 0; mf < 4; mf++)
#pragma unroll
                    for (int nf = 0; nf < 4; nf++)
                        mma_bf16(acc[mf][half * 4 + nf], ah[mf], bh0[nf], bh1[nf]);
                // term 3: Alo*Bhi (keeps bh live, then bh dead)
#pragma unroll
                for (int mf = 0; mf < 4; mf++)
#pragma unroll
                    for (int nf = 0; nf < 4; nf++)
                        mma_bf16(acc[mf][half * 4 + nf], al[mf], bh0[nf], bh1[nf]);
                // term 2: Ahi*Blo
#pragma unroll
                for (int mf = 0; mf < 4; mf++)
#pragma unroll
                    for (int nf = 0; nf < 4; nf++)
                        mma_bf16(acc[mf][half * 4 + nf], ah[mf], bl0[nf], bl1[nf]);
            }
        }
        cbuf ^= 1;
    }

    // ---- fused epilogue ----
    constexpr int OST = (EPI == 1) ? O_DIM : L_DIM;
    float* PART = (EPI == 0) ? OF1 + (size_t)blockIdx.z * B_DIM * L_DIM : nullptr;
#pragma unroll
    for (int mf = 0; mf < 4; mf++) {
#pragma unroll
        for (int nfa = 0; nfa < 8; nfa++) {
            int r0 = bm + wm * 64 + mf * 16 + (lane >> 2);
            int cc = bn + wn * 64 + (nfa >> 2) * 32 + (nfa & 3) * 8 + (lane & 3) * 2;
#pragma unroll
            for (int h = 0; h < 2; h++) {
                int r = r0 + h * 8;
                float d0 = acc[mf][nfa][2 * h], d1 = acc[mf][nfa][2 * h + 1];
                size_t off = (size_t)r * OST + cc;
                if (EPI == 1) {
                    float2 xv = *(const float2*)(X + off);
                    float p0 = tanhf(d0), p1 = tanhf(d1);
                    float g0 = (1.f - p0 * p0) * (xv.x - p0);
                    float g1 = (1.f - p1 * p1) * (xv.y - p1);
                    u16 h0, l0, h1, l1;
                    split2(g0, h0, l0); split2(g1, h1, l1);
                    *(u32*)(Ohi + off) = (u32)h0 | ((u32)h1 << 16);
                    *(u32*)(Olo + off) = (u32)l0 | ((u32)l1 << 16);
                } else {
                    *(float2*)(PART + off) = make_float2(d0, d1);
                }
            }
        }
    }
}

// -------- reduce split-K partials + fused z-update (deterministic order) ----
__global__ void reduce_z(const float* __restrict__ part, const float* __restrict__ mu,
                         float* __restrict__ zf, u16* __restrict__ zhi,
                         u16* __restrict__ zlo, float* __restrict__ out) {
    constexpr int ZN = B_DIM * L_DIM;
    int i = (blockIdx.x * blockDim.x + threadIdx.x) * 2;
    int l = i & (L_DIM - 1);
    float2 p0 = *(const float2*)(part + i);
    float2 p1 = *(const float2*)(part + ZN + i);
    float2 p2 = *(const float2*)(part + 2 * ZN + i);
    float2 p3 = *(const float2*)(part + 3 * ZN + i);
    float dx = (p0.x + p1.x) + (p2.x + p3.x);
    float dy = (p0.y + p1.y) + (p2.y + p3.y);
    float2 zv = *(const float2*)(zf + i);
    float2 mv = *(const float2*)(mu + l);
    float s0 = (float)((zv.x > 0.f) - (zv.x < 0.f));
    float s1 = (float)((zv.y > 0.f) - (zv.y < 0.f));
    float zn0 = zv.x - INF_LR * ((zv.x - mv.x) - dx + SPARSE_Z * s0);
    float zn1 = zv.y - INF_LR * ((zv.y - mv.y) - dy + SPARSE_Z * s1);
    *(float2*)(zf + i) = make_float2(zn0, zn1);
    u16 h0, l0, h1, l1;
    split2(zn0, h0, l0); split2(zn1, h1, l1);
    *(u32*)(zhi + i) = (u32)h0 | ((u32)h1 << 16);
    *(u32*)(zlo + i) = (u32)l0 | ((u32)l1 << 16);
    if (out) *(float2*)(out + i) = make_float2(zn0, zn1);
}

// ---------------- launch ----------------
extern "C" void kernel_launch(void* const* d_in, const int* in_sizes, int n_in,
                              void* d_out, int out_size) {
    const float* x  = (const float*)d_in[0];   // [B, O]
    const float* W  = (const float*)d_in[1];   // [O, L]
    const float* mu = (const float*)d_in[2];   // [L]
    // d_in[3] = inf_iters (device scalar; fixed at 20 by the problem spec)
    float* out = (float*)d_out;                // [B, L]

    u16 *Whi, *Wlo, *WThi, *WTlo, *Ghi, *Glo, *zhi, *zlo;
    float *zf, *part;
    cudaGetSymbolAddress((void**)&Whi,  g_Whi);
    cudaGetSymbolAddress((void**)&Wlo,  g_Wlo);
    cudaGetSymbolAddress((void**)&WThi, g_WThi);
    cudaGetSymbolAddress((void**)&WTlo, g_WTlo);
    cudaGetSymbolAddress((void**)&Ghi,  g_Ghi);
    cudaGetSymbolAddress((void**)&Glo,  g_Glo);
    cudaGetSymbolAddress((void**)&zf,   g_zf);
    cudaGetSymbolAddress((void**)&zhi,  g_zhi);
    cudaGetSymbolAddress((void**)&zlo,  g_zlo);
    cudaGetSymbolAddress((void**)&part, g_part);

    constexpr int SMEM = 2 * 2 * (128 * 128 + 256 * 128) + 256;  // 196864

    cudaFuncSetAttribute(gemm_big<1, L_DIM, L_DIM>,
                         cudaFuncAttributeMaxDynamicSharedMemorySize, SMEM);
    cudaFuncSetAttribute(gemm_big<0, O_DIM, 1024>,
                         cudaFuncAttributeMaxDynamicSharedMemorySize, SMEM);

    prep_w<<<dim3(L_DIM / 32, O_DIM / 32), dim3(32, 8)>>>(W, Whi, Wlo, WThi, WTlo);
    init_z<<<(B_DIM * L_DIM) / 256, 256>>>(mu, zf, zhi, zlo);

    for (int it = 0; it < N_ITERS; ++it) {
        // GEMM1: C[b,o] = z @ W^T; fused tanh-deriv epilogue -> G (bf16 hi/lo)
        gemm_big<1, L_DIM, L_DIM>
            <<<dim3(O_DIM / 256, B_DIM / 128, 1), 256, SMEM>>>(
                zhi, zlo, Whi, Wlo, x, Ghi, Glo, nullptr);

        // GEMM2: partial[b,l] per K-split of G @ W  (B-operand = WT[l,o])
        gemm_big<0, O_DIM, 1024>
            <<<dim3(L_DIM / 256, B_DIM / 128, 4), 256, SMEM>>>(
                Ghi, Glo, WThi, WTlo, nullptr, nullptr, nullptr, part);

        // deterministic 4-way reduce + fused z update
        reduce_z<<<(B_DIM * L_DIM / 2) / 256, 256>>>(
            part, mu, zf, zhi, zlo, (it == N_ITERS - 1) ? out : nullptr);
    }
}

// round 10
// speedup vs baseline: 1.6499x; 1.4943x over previous
#include <cuda_runtime.h>
#include <cuda_fp16.h>
#include <cstdint>
#include <stddef.h>
#include <math.h>

#define B_DIM 1024
#define L_DIM 1024
#define O_DIM 4096
#define N_ITERS 20
#define INF_LR   0.01f
#define SPARSE_Z 1e-3f

typedef unsigned short u16;
typedef uint32_t u32;

// ---------------- scratch (no cudaMalloc allowed) ----------------
__device__ u16   g_Whi [O_DIM * L_DIM];
__device__ u16   g_Wlo [O_DIM * L_DIM];
__device__ u16   g_WThi[L_DIM * O_DIM];
__device__ u16   g_WTlo[L_DIM * O_DIM];
__device__ u16   g_Gh  [B_DIM * O_DIM];
__device__ float g_zf  [B_DIM * L_DIM];
__device__ u16   g_zh  [B_DIM * L_DIM];
__device__ float g_part[4 * B_DIM * L_DIM];   // split-K partials (16MB)

// ---------------- helpers ----------------
__device__ __forceinline__ u32 smem_u32(const void* p) {
    u32 a;
    asm("{ .reg .u64 t; cvta.to.shared.u64 t, %1; cvt.u32.u64 %0, t; }" : "=r"(a) : "l"(p));
    return a;
}
__device__ __forceinline__ void cp16(u32 dst, const void* src) {
    asm volatile("cp.async.cg.shared.global [%0], [%1], 16;" :: "r"(dst), "l"(src));
}
__device__ __forceinline__ void cp_commit() { asm volatile("cp.async.commit_group;"); }
template <int N> __device__ __forceinline__ void cp_wait() {
    asm volatile("cp.async.wait_group %0;" :: "n"(N));
}
__device__ __forceinline__ void ldsm4(u32* r, u32 a) {
    asm volatile("ldmatrix.sync.aligned.m8n8.x4.shared.b16 {%0,%1,%2,%3}, [%4];"
                 : "=r"(r[0]), "=r"(r[1]), "=r"(r[2]), "=r"(r[3]) : "r"(a));
}
__device__ __forceinline__ void mma_f16(float* d, const u32* a, u32 b0, u32 b1) {
    asm volatile(
        "mma.sync.aligned.m16n8k16.row.col.f32.f16.f16.f32 "
        "{%0,%1,%2,%3},{%4,%5,%6,%7},{%8,%9},{%0,%1,%2,%3};"
        : "+f"(d[0]), "+f"(d[1]), "+f"(d[2]), "+f"(d[3])
        : "r"(a[0]), "r"(a[1]), "r"(a[2]), "r"(a[3]), "r"(b0), "r"(b1));
}
__device__ __forceinline__ u16 f2h(float v) {
    return __half_as_ushort(__float2half_rn(v));
}
__device__ __forceinline__ void splitH(float v, u16& h, u16& l) {
    __half hh = __float2half_rn(v);
    h = __half_as_ushort(hh);
    l = f2h(v - __half2float(hh));
}
__device__ __forceinline__ u32 swz(u32 off) { return off ^ ((off >> 3) & 0x70u); }

// ---------------- one-time prep ----------------
__global__ void prep_w(const float* __restrict__ W,
                       u16* __restrict__ Whi, u16* __restrict__ Wlo,
                       u16* __restrict__ WThi, u16* __restrict__ WTlo) {
    __shared__ float t[32][33];
    int tx = threadIdx.x, ty = threadIdx.y;
    int lx = blockIdx.x * 32, oy = blockIdx.y * 32;
#pragma unroll
    for (int r = 0; r < 32; r += 8) {
        size_t idx = (size_t)(oy + ty + r) * L_DIM + lx + tx;
        float v = W[idx];
        u16 h, l; splitH(v, h, l);
        Whi[idx] = h; Wlo[idx] = l;
        t[ty + r][tx] = v;
    }
    __syncthreads();
#pragma unroll
    for (int r = 0; r < 32; r += 8) {
        float v = t[tx][ty + r];
        size_t idx = (size_t)(lx + ty + r) * O_DIM + oy + tx;
        u16 h, l; splitH(v, h, l);
        WThi[idx] = h; WTlo[idx] = l;
    }
}

__global__ void init_z(const float* __restrict__ mu, float* __restrict__ zf,
                       u16* __restrict__ zh) {
    int i = blockIdx.x * blockDim.x + threadIdx.x;
    float v = mu[i & (L_DIM - 1)];
    zf[i] = v;
    zh[i] = f2h(v);
}

// ------------- big-warp-tile fp16 split-GEMM (CTA 128x256, warp 64x64) ------
// C[m,n] = sum_k A[m,k]*B[n,k]; 2-term split: Ah*(Bh + Bl).
// A = activations (fp16 only), B = weights (fp16 hi/lo pair, ~exact).
// KROW: global K stride. KLEN: K span per CTA (blockIdx.z = split-K chunk).
// EPI=1: p=tanh(C); g=(1-p^2)*(X-p); write g as fp16 (Oh).
// EPI=0: write raw fp32 partial to OF1 + blockIdx.z*(B*L).
template <int EPI, int KROW, int KLEN>
__global__ void __launch_bounds__(256, 1)
gemm_big(const u16* __restrict__ Ah, const u16* __restrict__ Bh,
         const u16* __restrict__ Bl, const float* __restrict__ X,
         u16* __restrict__ Oh, float* __restrict__ OF1) {
    constexpr int BM = 128, BN = 256, BK = 64, ROWB = 128;
    constexpr int ABYTES = BM * ROWB;              // 16384
    constexpr int BBYTES = BN * ROWB;              // 32768
    constexpr int STAGE  = ABYTES + 2 * BBYTES;    // 81920
    constexpr int CPA = ABYTES / 16, CPB = BBYTES / 16;
    constexpr int TOT = CPA + 2 * CPB;             // 5120
    constexpr int S = KLEN / BK;                   // 16

    extern __shared__ char sraw[];
    const u32 smem0 = (smem_u32(sraw) + 127u) & ~127u;

    const int tid = threadIdx.x, lane = tid & 31, wid = tid >> 5;
    const int wm = wid >> 2, wn = wid & 3;     // 2 x 4 warps, warp tile 64x64
    const int bm = blockIdx.y * BM, bn = blockIdx.x * BN;
    const int kbase = blockIdx.z * S;

    auto load_stage = [&](int s, int buf) {
        const u32 sb = smem0 + (u32)buf * STAGE;
        const int k0 = (kbase + s) * BK;
#pragma unroll
        for (int i = 0; i < TOT / 256; i++) {
            int c = tid + i * 256;
            const u16* src; u32 tb; int local, rowbase;
            if (c < CPA)            { src = Ah; tb = sb;                    local = c;             rowbase = bm; }
            else if (c < CPA + CPB) { src = Bh; tb = sb + ABYTES;           local = c - CPA;       rowbase = bn; }
            else                    { src = Bl; tb = sb + ABYTES + BBYTES;  local = c - CPA - CPB; rowbase = bn; }
            int row = local >> 3, c16 = local & 7;
            cp16(tb + swz((u32)(row * ROWB + c16 * 16)),
                 src + (size_t)(rowbase + row) * KROW + k0 + c16 * 8);
        }
    };

    float acc[4][8][4];
#pragma unroll
    for (int a = 0; a < 4; a++)
#pragma unroll
        for (int b = 0; b < 8; b++)
#pragma unroll
            for (int k = 0; k < 4; k++) acc[a][b][k] = 0.f;

    // ldmatrix address components
    const u32 sx   = ((u32)(lane & 7)) << 4;                 // swizzle XOR
    const u32 aOff = (u32)((wm * 64 + (lane & 15)) * ROWB);  // +mf*16*ROWB
    const u32 aK   = ((u32)(lane >> 4)) << 4;
    const u32 bOff = (u32)((wn * 64 + lane) * ROWB);         // +half*32*ROWB

    load_stage(0, 0); cp_commit();

    int cbuf = 0, lbuf = 1;
    for (int s = 0; s < S; s++) {
        cp_wait<0>();
        __syncthreads();
        if (s + 1 < S) load_stage(s + 1, lbuf);
        cp_commit();
        lbuf ^= 1;

        const u32 sb = smem0 + (u32)cbuf * STAGE;
        const u32 sAh = sb;
        const u32 sBh = sb + ABYTES, sBl = sb + ABYTES + BBYTES;
#pragma unroll
        for (int ks = 0; ks < BK / 16; ks++) {
            const u32 ko  = (((u32)(ks * 32) + aK) ^ sx);
            const u32 k0o = (((u32)(ks * 32)) ^ sx);
            const u32 k1o = (((u32)(ks * 32 + 16)) ^ sx);

            u32 ah[4][4];
#pragma unroll
            for (int mf = 0; mf < 4; mf++)
                ldsm4(ah[mf], sAh + aOff + (u32)(mf * 16 * ROWB) + ko);
#pragma unroll
            for (int half = 0; half < 2; half++) {
                const u32 bo = bOff + (u32)(half * 32 * ROWB);
                u32 bh0[4], bh1[4], bl0[4], bl1[4];
                ldsm4(bh0, sBh + bo + k0o);
                ldsm4(bh1, sBh + bo + k1o);
                ldsm4(bl0, sBl + bo + k0o);
                ldsm4(bl1, sBl + bo + k1o);
                // term 1: Ah*Bh
#pragma unroll
                for (int mf = 0; mf < 4; mf++)
#pragma unroll
                    for (int nf = 0; nf < 4; nf++)
                        mma_f16(acc[mf][half * 4 + nf], ah[mf], bh0[nf], bh1[nf]);
                // term 2: Ah*Bl
#pragma unroll
                for (int mf = 0; mf < 4; mf++)
#pragma unroll
                    for (int nf = 0; nf < 4; nf++)
                        mma_f16(acc[mf][half * 4 + nf], ah[mf], bl0[nf], bl1[nf]);
            }
        }
        cbuf ^= 1;
    }

    // ---- fused epilogue ----
    constexpr int OST = (EPI == 1) ? O_DIM : L_DIM;
    float* PART = (EPI == 0) ? OF1 + (size_t)blockIdx.z * B_DIM * L_DIM : nullptr;
#pragma unroll
    for (int mf = 0; mf < 4; mf++) {
#pragma unroll
        for (int nfa = 0; nfa < 8; nfa++) {
            int r0 = bm + wm * 64 + mf * 16 + (lane >> 2);
            int cc = bn + wn * 64 + (nfa >> 2) * 32 + (nfa & 3) * 8 + (lane & 3) * 2;
#pragma unroll
            for (int h = 0; h < 2; h++) {
                int r = r0 + h * 8;
                float d0 = acc[mf][nfa][2 * h], d1 = acc[mf][nfa][2 * h + 1];
                size_t off = (size_t)r * OST + cc;
                if (EPI == 1) {
                    float2 xv = *(const float2*)(X + off);
                    float p0 = tanhf(d0), p1 = tanhf(d1);
                    float g0 = (1.f - p0 * p0) * (xv.x - p0);
                    float g1 = (1.f - p1 * p1) * (xv.y - p1);
                    *(u32*)(Oh + off) = (u32)f2h(g0) | ((u32)f2h(g1) << 16);
                } else {
                    *(float2*)(PART + off) = make_float2(d0, d1);
                }
            }
        }
    }
}

// -------- reduce split-K partials + fused z-update (deterministic order) ----
__global__ void reduce_z(const float* __restrict__ part, const float* __restrict__ mu,
                         float* __restrict__ zf, u16* __restrict__ zh,
                         float* __restrict__ out) {
    constexpr int ZN = B_DIM * L_DIM;
    int i = (blockIdx.x * blockDim.x + threadIdx.x) * 2;
    int l = i & (L_DIM - 1);
    float2 p0 = *(const float2*)(part + i);
    float2 p1 = *(const float2*)(part + ZN + i);
    float2 p2 = *(const float2*)(part + 2 * ZN + i);
    float2 p3 = *(const float2*)(part + 3 * ZN + i);
    float dx = (p0.x + p1.x) + (p2.x + p3.x);
    float dy = (p0.y + p1.y) + (p2.y + p3.y);
    float2 zv = *(const float2*)(zf + i);
    float2 mv = *(const float2*)(mu + l);
    float s0 = (float)((zv.x > 0.f) - (zv.x < 0.f));
    float s1 = (float)((zv.y > 0.f) - (zv.y < 0.f));
    float zn0 = zv.x - INF_LR * ((zv.x - mv.x) - dx + SPARSE_Z * s0);
    float zn1 = zv.y - INF_LR * ((zv.y - mv.y) - dy + SPARSE_Z * s1);
    *(float2*)(zf + i) = make_float2(zn0, zn1);
    *(u32*)(zh + i) = (u32)f2h(zn0) | ((u32)f2h(zn1) << 16);
    if (out) *(float2*)(out + i) = make_float2(zn0, zn1);
}

// ---------------- launch ----------------
extern "C" void kernel_launch(void* const* d_in, const int* in_sizes, int n_in,
                              void* d_out, int out_size) {
    const float* x  = (const float*)d_in[0];   // [B, O]
    const float* W  = (const float*)d_in[1];   // [O, L]
    const float* mu = (const float*)d_in[2];   // [L]
    // d_in[3] = inf_iters (device scalar; fixed at 20 by the problem spec)
    float* out = (float*)d_out;                // [B, L]

    u16 *Whi, *Wlo, *WThi, *WTlo, *Gh, *zh;
    float *zf, *part;
    cudaGetSymbolAddress((void**)&Whi,  g_Whi);
    cudaGetSymbolAddress((void**)&Wlo,  g_Wlo);
    cudaGetSymbolAddress((void**)&WThi, g_WThi);
    cudaGetSymbolAddress((void**)&WTlo, g_WTlo);
    cudaGetSymbolAddress((void**)&Gh,   g_Gh);
    cudaGetSymbolAddress((void**)&zf,   g_zf);
    cudaGetSymbolAddress((void**)&zh,   g_zh);
    cudaGetSymbolAddress((void**)&part, g_part);

    // STAGE = A(128*128B) + 2*B(256*128B) = 81920 B; 2 stages + pad = 164096 B
    constexpr int STAGE = 128 * 128 + 2 * 256 * 128;   // bytes (u16 elems * 2 folded in ROWB)
    constexpr int SMEM  = 2 * STAGE + 256;             // 164096 — fits 227KB cap

    cudaFuncSetAttribute(gemm_big<1, L_DIM, L_DIM>,
                         cudaFuncAttributeMaxDynamicSharedMemorySize, SMEM);
    cudaFuncSetAttribute(gemm_big<0, O_DIM, 1024>,
                         cudaFuncAttributeMaxDynamicSharedMemorySize, SMEM);

    prep_w<<<dim3(L_DIM / 32, O_DIM / 32), dim3(32, 8)>>>(W, Whi, Wlo, WThi, WTlo);
    init_z<<<(B_DIM * L_DIM) / 256, 256>>>(mu, zf, zh);

    for (int it = 0; it < N_ITERS; ++it) {
        // GEMM1: C[b,o] = z @ W^T; fused tanh-deriv epilogue -> G (fp16)
        gemm_big<1, L_DIM, L_DIM>
            <<<dim3(O_DIM / 256, B_DIM / 128, 1), 256, SMEM>>>(
                zh, Whi, Wlo, x, Gh, nullptr);

        // GEMM2: partial[b,l] per K-split of G @ W (B-operand = WT[l,o])
        gemm_big<0, O_DIM, 1024>
            <<<dim3(L_DIM / 256, B_DIM / 128, 4), 256, SMEM>>>(
                Gh, WThi, WTlo, nullptr, nullptr, part);

        // deterministic 4-way reduce + fused z update
        reduce_z<<<(B_DIM * L_DIM / 2) / 256, 256>>>(
            part, mu, zf, zh, (it == N_ITERS - 1) ? out : nullptr);
    }
}

// round 11
// speedup vs baseline: 2.8528x; 1.7290x over previous
#include <cuda_runtime.h>
#include <cuda_fp16.h>
#include <cstdint>
#include <stddef.h>
#include <math.h>

#define B_DIM 1024
#define L_DIM 1024
#define O_DIM 4096
#define N_ITERS 20
#define INF_LR   0.01f
#define SPARSE_Z 1e-3f

typedef unsigned short u16;
typedef uint32_t u32;

// ---------------- scratch (no cudaMalloc allowed) ----------------
__device__ u16   g_Wh  [O_DIM * L_DIM];
__device__ u16   g_WTh [L_DIM * O_DIM];
__device__ u16   g_Gh  [B_DIM * O_DIM];
__device__ float g_zf  [B_DIM * L_DIM];
__device__ u16   g_zh  [B_DIM * L_DIM];
__device__ float g_part[4 * B_DIM * L_DIM];   // split-K partials (16MB)

// ---------------- helpers ----------------
__device__ __forceinline__ u32 smem_u32(const void* p) {
    u32 a;
    asm("{ .reg .u64 t; cvta.to.shared.u64 t, %1; cvt.u32.u64 %0, t; }" : "=r"(a) : "l"(p));
    return a;
}
__device__ __forceinline__ void cp16(u32 dst, const void* src) {
    asm volatile("cp.async.cg.shared.global [%0], [%1], 16;" :: "r"(dst), "l"(src));
}
__device__ __forceinline__ void cp_commit() { asm volatile("cp.async.commit_group;"); }
template <int N> __device__ __forceinline__ void cp_wait() {
    asm volatile("cp.async.wait_group %0;" :: "n"(N));
}
__device__ __forceinline__ void ldsm4(u32* r, u32 a) {
    asm volatile("ldmatrix.sync.aligned.m8n8.x4.shared.b16 {%0,%1,%2,%3}, [%4];"
                 : "=r"(r[0]), "=r"(r[1]), "=r"(r[2]), "=r"(r[3]) : "r"(a));
}
__device__ __forceinline__ void mma_f16(float* d, const u32* a, u32 b0, u32 b1) {
    asm volatile(
        "mma.sync.aligned.m16n8k16.row.col.f32.f16.f16.f32 "
        "{%0,%1,%2,%3},{%4,%5,%6,%7},{%8,%9},{%0,%1,%2,%3};"
        : "+f"(d[0]), "+f"(d[1]), "+f"(d[2]), "+f"(d[3])
        : "r"(a[0]), "r"(a[1]), "r"(a[2]), "r"(a[3]), "r"(b0), "r"(b1));
}
__device__ __forceinline__ u16 f2h(float v) {
    return __half_as_ushort(__float2half_rn(v));
}
__device__ __forceinline__ u32 swz(u32 off) { return off ^ ((off >> 3) & 0x70u); }

// ---------------- one-time prep ----------------
// W[O,L] -> fp16 Wh; transpose -> fp16 WTh[L,O].
__global__ void prep_w(const float* __restrict__ W,
                       u16* __restrict__ Wh, u16* __restrict__ WTh) {
    __shared__ float t[32][33];
    int tx = threadIdx.x, ty = threadIdx.y;
    int lx = blockIdx.x * 32, oy = blockIdx.y * 32;
#pragma unroll
    for (int r = 0; r < 32; r += 8) {
        size_t idx = (size_t)(oy + ty + r) * L_DIM + lx + tx;
        float v = W[idx];
        Wh[idx] = f2h(v);
        t[ty + r][tx] = v;
    }
    __syncthreads();
#pragma unroll
    for (int r = 0; r < 32; r += 8) {
        float v = t[tx][ty + r];
        size_t idx = (size_t)(lx + ty + r) * O_DIM + oy + tx;
        WTh[idx] = f2h(v);
    }
}

__global__ void init_z(const float* __restrict__ mu, float* __restrict__ zf,
                       u16* __restrict__ zh) {
    int i = blockIdx.x * blockDim.x + threadIdx.x;
    float v = mu[i & (L_DIM - 1)];
    zf[i] = v;
    zh[i] = f2h(v);
}

// ------------- big-warp-tile fp16 GEMM (CTA 128x256, warp 64x64) ------------
// C[m,n] = sum_k A[m,k]*B[n,k]; plain fp16 operands, fp32 accumulate.
// KROW: global K stride. KLEN: K span per CTA (blockIdx.z = split-K chunk).
// EPI=1: p=tanh(C); g=(1-p^2)*(X-p); write g as fp16 (Oh).
// EPI=0: write raw fp32 partial to OF1 + blockIdx.z*(B*L).
template <int EPI, int KROW, int KLEN>
__global__ void __launch_bounds__(256, 1)
gemm_big(const u16* __restrict__ Ah, const u16* __restrict__ Bh,
         const float* __restrict__ X,
         u16* __restrict__ Oh, float* __restrict__ OF1) {
    constexpr int BM = 128, BN = 256, BK = 64, ROWB = 128;
    constexpr int ABYTES = BM * ROWB;          // 16384
    constexpr int BBYTES = BN * ROWB;          // 32768
    constexpr int STAGE  = ABYTES + BBYTES;    // 49152
    constexpr int CPA = ABYTES / 16, CPB = BBYTES / 16;
    constexpr int TOT = CPA + CPB;             // 3072
    constexpr int S = KLEN / BK;               // 16

    extern __shared__ char sraw[];
    const u32 smem0 = (smem_u32(sraw) + 127u) & ~127u;

    const int tid = threadIdx.x, lane = tid & 31, wid = tid >> 5;
    const int wm = wid >> 2, wn = wid & 3;     // 2 x 4 warps, warp tile 64x64
    const int bm = blockIdx.y * BM, bn = blockIdx.x * BN;
    const int kbase = blockIdx.z * S;

    auto load_stage = [&](int s, int buf) {
        const u32 sb = smem0 + (u32)buf * STAGE;
        const int k0 = (kbase + s) * BK;
#pragma unroll
        for (int i = 0; i < TOT / 256; i++) {
            int c = tid + i * 256;
            const u16* src; u32 tb; int local, rowbase;
            if (c < CPA) { src = Ah; tb = sb;          local = c;       rowbase = bm; }
            else         { src = Bh; tb = sb + ABYTES; local = c - CPA; rowbase = bn; }
            int row = local >> 3, c16 = local & 7;
            cp16(tb + swz((u32)(row * ROWB + c16 * 16)),
                 src + (size_t)(rowbase + row) * KROW + k0 + c16 * 8);
        }
    };

    float acc[4][8][4];
#pragma unroll
    for (int a = 0; a < 4; a++)
#pragma unroll
        for (int b = 0; b < 8; b++)
#pragma unroll
            for (int k = 0; k < 4; k++) acc[a][b][k] = 0.f;

    // ldmatrix address components
    const u32 sx   = ((u32)(lane & 7)) << 4;                 // swizzle XOR
    const u32 aOff = (u32)((wm * 64 + (lane & 15)) * ROWB);  // +mf*16*ROWB
    const u32 aK   = ((u32)(lane >> 4)) << 4;
    const u32 bOff = (u32)((wn * 64 + lane) * ROWB);         // +half*32*ROWB

    load_stage(0, 0); cp_commit();

    int cbuf = 0, lbuf = 1;
    for (int s = 0; s < S; s++) {
        cp_wait<0>();
        __syncthreads();
        if (s + 1 < S) load_stage(s + 1, lbuf);
        cp_commit();
        lbuf ^= 1;

        const u32 sb = smem0 + (u32)cbuf * STAGE;
        const u32 sAh = sb, sBh = sb + ABYTES;
#pragma unroll
        for (int ks = 0; ks < BK / 16; ks++) {
            const u32 ko  = (((u32)(ks * 32) + aK) ^ sx);
            const u32 k0o = (((u32)(ks * 32)) ^ sx);
            const u32 k1o = (((u32)(ks * 32 + 16)) ^ sx);

            u32 ah[4][4];
#pragma unroll
            for (int mf = 0; mf < 4; mf++)
                ldsm4(ah[mf], sAh + aOff + (u32)(mf * 16 * ROWB) + ko);
#pragma unroll
            for (int half = 0; half < 2; half++) {
                const u32 bo = bOff + (u32)(half * 32 * ROWB);
                u32 b0[4], b1[4];
                ldsm4(b0, sBh + bo + k0o);
                ldsm4(b1, sBh + bo + k1o);
#pragma unroll
                for (int mf = 0; mf < 4; mf++)
#pragma unroll
                    for (int nf = 0; nf < 4; nf++)
                        mma_f16(acc[mf][half * 4 + nf], ah[mf], b0[nf], b1[nf]);
            }
        }
        cbuf ^= 1;
    }

    // ---- fused epilogue ----
    constexpr int OST = (EPI == 1) ? O_DIM : L_DIM;
    float* PART = (EPI == 0) ? OF1 + (size_t)blockIdx.z * B_DIM * L_DIM : nullptr;
#pragma unroll
    for (int mf = 0; mf < 4; mf++) {
#pragma unroll
        for (int nfa = 0; nfa < 8; nfa++) {
            int r0 = bm + wm * 64 + mf * 16 + (lane >> 2);
            int cc = bn + wn * 64 + (nfa >> 2) * 32 + (nfa & 3) * 8 + (lane & 3) * 2;
#pragma unroll
            for (int h = 0; h < 2; h++) {
                int r = r0 + h * 8;
                float d0 = acc[mf][nfa][2 * h], d1 = acc[mf][nfa][2 * h + 1];
                size_t off = (size_t)r * OST + cc;
                if (EPI == 1) {
                    float2 xv = *(const float2*)(X + off);
                    float p0 = tanhf(d0), p1 = tanhf(d1);
                    float g0 = (1.f - p0 * p0) * (xv.x - p0);
                    float g1 = (1.f - p1 * p1) * (xv.y - p1);
                    *(u32*)(Oh + off) = (u32)f2h(g0) | ((u32)f2h(g1) << 16);
                } else {
                    *(float2*)(PART + off) = make_float2(d0, d1);
                }
            }
        }
    }
}

// -------- reduce split-K partials + fused z-update (deterministic order) ----
__global__ void reduce_z(const float* __restrict__ part, const float* __restrict__ mu,
                         float* __restrict__ zf, u16* __restrict__ zh,
                         float* __restrict__ out) {
    constexpr int ZN = B_DIM * L_DIM;
    int i = (blockIdx.x * blockDim.x + threadIdx.x) * 2;
    int l = i & (L_DIM - 1);
    float2 p0 = *(const float2*)(part + i);
    float2 p1 = *(const float2*)(part + ZN + i);
    float2 p2 = *(const float2*)(part + 2 * ZN + i);
    float2 p3 = *(const float2*)(part + 3 * ZN + i);
    float dx = (p0.x + p1.x) + (p2.x + p3.x);
    float dy = (p0.y + p1.y) + (p2.y + p3.y);
    float2 zv = *(const float2*)(zf + i);
    float2 mv = *(const float2*)(mu + l);
    float s0 = (float)((zv.x > 0.f) - (zv.x < 0.f));
    float s1 = (float)((zv.y > 0.f) - (zv.y < 0.f));
    float zn0 = zv.x - INF_LR * ((zv.x - mv.x) - dx + SPARSE_Z * s0);
    float zn1 = zv.y - INF_LR * ((zv.y - mv.y) - dy + SPARSE_Z * s1);
    *(float2*)(zf + i) = make_float2(zn0, zn1);
    *(u32*)(zh + i) = (u32)f2h(zn0) | ((u32)f2h(zn1) << 16);
    if (out) *(float2*)(out + i) = make_float2(zn0, zn1);
}

// ---------------- launch ----------------
extern "C" void kernel_launch(void* const* d_in, const int* in_sizes, int n_in,
                              void* d_out, int out_size) {
    const float* x  = (const float*)d_in[0];   // [B, O]
    const float* W  = (const float*)d_in[1];   // [O, L]
    const float* mu = (const float*)d_in[2];   // [L]
    // d_in[3] = inf_iters (device scalar; fixed at 20 by the problem spec)
    float* out = (float*)d_out;                // [B, L]

    u16 *Wh, *WTh, *Gh, *zh;
    float *zf, *part;
    cudaGetSymbolAddress((void**)&Wh,   g_Wh);
    cudaGetSymbolAddress((void**)&WTh,  g_WTh);
    cudaGetSymbolAddress((void**)&Gh,   g_Gh);
    cudaGetSymbolAddress((void**)&zf,   g_zf);
    cudaGetSymbolAddress((void**)&zh,   g_zh);
    cudaGetSymbolAddress((void**)&part, g_part);

    // STAGE = A(16KB) + B(32KB) = 49152 B; 2 stages + pad = 98560 B
    constexpr int STAGE = 128 * 128 + 256 * 128;
    constexpr int SMEM  = 2 * STAGE + 256;

    cudaFuncSetAttribute(gemm_big<1, L_DIM, L_DIM>,
                         cudaFuncAttributeMaxDynamicSharedMemorySize, SMEM);
    cudaFuncSetAttribute(gemm_big<0, O_DIM, 1024>,
                         cudaFuncAttributeMaxDynamicSharedMemorySize, SMEM);

    prep_w<<<dim3(L_DIM / 32, O_DIM / 32), dim3(32, 8)>>>(W, Wh, WTh);
    init_z<<<(B_DIM * L_DIM) / 256, 256>>>(mu, zf, zh);

    for (int it = 0; it < N_ITERS; ++it) {
        // GEMM1: C[b,o] = z @ W^T; fused tanh-deriv epilogue -> G (fp16)
        gemm_big<1, L_DIM, L_DIM>
            <<<dim3(O_DIM / 256, B_DIM / 128, 1), 256, SMEM>>>(
                zh, Wh, x, Gh, nullptr);

        // GEMM2: partial[b,l] per K-split of G @ W (B-operand = WT[l,o])
        gemm_big<0, O_DIM, 1024>
            <<<dim3(L_DIM / 256, B_DIM / 128, 4), 256, SMEM>>>(
                Gh, WTh, nullptr, nullptr, part);

        // deterministic 4-way reduce + fused z update
        reduce_z<<<(B_DIM * L_DIM / 2) / 256, 256>>>(
            part, mu, zf, zh, (it == N_ITERS - 1) ? out : nullptr);
    }
}